// round 6
// baseline (speedup 1.0000x reference)
#include <cuda_runtime.h>
#include <cuda_bf16.h>
#include <math.h>

#define NN   50000
#define HID  64
#define EE   800000
#define EP   100000
#define LYR  2
#define BN_EPS 1e-5f
#define NB_SCAN 196            // 196 * 256 = 50176 >= NN

// ---------------- scratch ----------------
__device__ float g_x[NN * HID];
__device__ float g_agg[NN * HID];
__device__ float g_dis[NN];
__device__ int   g_deg[NN];
__device__ int   g_cnt[NN];
__device__ int   g_row_start[NN + 1];
__device__ int   g_csr_src[EE];
__device__ float g_csr_w[EE];
__device__ int   g_part[256];
__device__ float g_stats[LYR * 2 * HID];   // per layer: [0:64) sum, [64:128) sumsq

// ---------------- init: deg=1 (self loop), counters, stats ----------------
__global__ void k_init() {
    int n = blockIdx.x * blockDim.x + threadIdx.x;
    if (n < NN) { g_deg[n] = 1; g_cnt[n] = 0; }
    if (n < LYR * 2 * HID) g_stats[n] = 0.f;
    if (n == 0) g_row_start[NN] = EE;
}

__global__ void k_deg_count(const int* __restrict__ ei) {
    int e = blockIdx.x * blockDim.x + threadIdx.x;
    if (e < EE) atomicAdd(&g_deg[ei[EE + e]], 1);
}

// block partial sums of (deg-1), fused with dis = rsqrt(deg)
__global__ void k_scan_part() {
    __shared__ int sh[256];
    int t = threadIdx.x;
    int idx = blockIdx.x * 256 + t;
    int d = (idx < NN) ? g_deg[idx] : 1;
    if (idx < NN) g_dis[idx] = rsqrtf((float)d);
    sh[t] = d - 1;
    __syncthreads();
    for (int o = 128; o > 0; o >>= 1) {
        if (t < o) sh[t] += sh[t + o];
        __syncthreads();
    }
    if (t == 0) g_part[blockIdx.x] = sh[0];
}

// row_start: per-block exclusive scan + inline scan of block partials
__global__ void k_scan_write() {
    __shared__ int shp[256];
    __shared__ int sh[256];
    int t = threadIdx.x;
    int pv = (t < NB_SCAN) ? g_part[t] : 0;
    shp[t] = pv;
    __syncthreads();
    for (int o = 1; o < 256; o <<= 1) {
        int s = (t >= o) ? shp[t - o] : 0;
        __syncthreads();
        shp[t] += s;
        __syncthreads();
    }
    int boff = shp[blockIdx.x] - g_part[blockIdx.x];   // exclusive offset of this block

    int idx = blockIdx.x * 256 + t;
    int v = (idx < NN) ? g_deg[idx] - 1 : 0;
    sh[t] = v;
    __syncthreads();
    for (int o = 1; o < 256; o <<= 1) {
        int s = (t >= o) ? sh[t - o] : 0;
        __syncthreads();
        sh[t] += s;
        __syncthreads();
    }
    if (idx < NN) g_row_start[idx] = boff + sh[t] - v;
}

__global__ void k_csr_fill(const int* __restrict__ ei) {
    int e = blockIdx.x * blockDim.x + threadIdx.x;
    if (e >= EE) return;
    int r = __ldg(ei + e);
    int c = __ldg(ei + EE + e);
    int pos = g_row_start[c] + atomicAdd(&g_cnt[c], 1);
    g_csr_src[pos] = r;
    g_csr_w[pos] = __ldg(g_dis + r) * __ldg(g_dis + c);
}

// ============ GEMM helpers: 128x64 block tile, 8x4 thread tile ============
__device__ __forceinline__ void mm_accum8(const float* Xs, const float* Ws,
                                          int n0, int c0, float4 acc[8]) {
#pragma unroll
    for (int k = 0; k < 64; k += 4) {
        float4 wv0 = *reinterpret_cast<const float4*>(Ws + (k + 0) * 64 + c0);
        float4 wv1 = *reinterpret_cast<const float4*>(Ws + (k + 1) * 64 + c0);
        float4 wv2 = *reinterpret_cast<const float4*>(Ws + (k + 2) * 64 + c0);
        float4 wv3 = *reinterpret_cast<const float4*>(Ws + (k + 3) * 64 + c0);
#pragma unroll
        for (int i = 0; i < 8; i++) {
            float4 xv = *reinterpret_cast<const float4*>(Xs + (n0 + i) * 64 + k);
            acc[i].x += xv.x * wv0.x + xv.y * wv1.x + xv.z * wv2.x + xv.w * wv3.x;
            acc[i].y += xv.x * wv0.y + xv.y * wv1.y + xv.z * wv2.y + xv.w * wv3.y;
            acc[i].z += xv.x * wv0.z + xv.y * wv1.z + xv.z * wv2.z + xv.w * wv3.z;
            acc[i].w += xv.x * wv0.w + xv.y * wv1.w + xv.z * wv2.w + xv.w * wv3.w;
        }
    }
}

// ---------------- input projection: x = [id|n2v] @ W + b ----------------
__global__ __launch_bounds__(256) void k_proj(const float* __restrict__ id_emb,
                                              const float* __restrict__ n2v_emb,
                                              const float* __restrict__ W,
                                              const float* __restrict__ b) {
    __shared__ float Xs[128 * 64];
    __shared__ float Ws[64 * 64];
    int tid = threadIdx.x;
    int base = blockIdx.x * 128;
    int c0 = (tid & 15) * 4, n0 = (tid >> 4) * 8;

    float4 acc[8];
#pragma unroll
    for (int i = 0; i < 8; i++) acc[i] = make_float4(0.f, 0.f, 0.f, 0.f);

#pragma unroll
    for (int chunk = 0; chunk < 2; chunk++) {
        const float* src = chunk ? n2v_emb : id_emb;
        for (int j = tid; j < 128 * 16; j += 256) {
            int gn = base + (j >> 4);
            float4 v = make_float4(0.f, 0.f, 0.f, 0.f);
            if (gn < NN) v = *reinterpret_cast<const float4*>(src + gn * 64 + (j & 15) * 4);
            *reinterpret_cast<float4*>(Xs + j * 4) = v;
        }
        const float* Wsrc = W + chunk * 64 * 64;
        for (int j = tid; j < 1024; j += 256)
            *reinterpret_cast<float4*>(Ws + j * 4) =
                *reinterpret_cast<const float4*>(Wsrc + j * 4);
        __syncthreads();
        mm_accum8(Xs, Ws, n0, c0, acc);
        __syncthreads();
    }

    float4 b4 = *reinterpret_cast<const float4*>(b + c0);
#pragma unroll
    for (int i = 0; i < 8; i++) {
        int gn = base + n0 + i;
        if (gn < NN) {
            float4 o = make_float4(acc[i].x + b4.x, acc[i].y + b4.y,
                                   acc[i].z + b4.z, acc[i].w + b4.w);
            *reinterpret_cast<float4*>(g_x + gn * 64 + c0) = o;
        }
    }
}

// ---------------- fused layer: gather(x) in smem -> GEMM -> agg + BN stats ------
// G[n] = dis[n]^2 * x[n] + sum_e w_e * x[src_e];  agg = G @ W + b
// smem = Xs (32KB) + Ws (16KB) = exactly 48KB; s_stats aliases Ws after the GEMM.
__global__ __launch_bounds__(256) void k_agg(const float* __restrict__ W,
                                             const float* __restrict__ conv_b,
                                             int layer) {
    __shared__ float Xs[128 * 64];
    __shared__ float Ws[64 * 64];
    int tid = threadIdx.x;
    int base = blockIdx.x * 128;
    int warp = tid >> 5, lane = tid & 31;

    for (int j = tid; j < 1024; j += 256)
        *reinterpret_cast<float4*>(Ws + j * 4) =
            *reinterpret_cast<const float4*>(W + j * 4);

    // gather phase: warp per node, 16 nodes per warp
    for (int nl = warp; nl < 128; nl += 8) {
        int n = base + nl;
        float2 acc = make_float2(0.f, 0.f);
        if (n < NN) {
            int s0 = __ldg(g_row_start + n);
            int s1 = __ldg(g_row_start + n + 1);
            float d = __ldg(g_dis + n);
            float sl = d * d;
            float2 xv = *reinterpret_cast<const float2*>(g_x + n * 64 + lane * 2);
            acc.x = sl * xv.x;
            acc.y = sl * xv.y;
            int e = s0;
            for (; e + 1 < s1; e += 2) {
                int   sa = __ldg(g_csr_src + e);
                float wa = __ldg(g_csr_w + e);
                int   sb = __ldg(g_csr_src + e + 1);
                float wb = __ldg(g_csr_w + e + 1);
                float2 ha = *reinterpret_cast<const float2*>(g_x + sa * 64 + lane * 2);
                float2 hb = *reinterpret_cast<const float2*>(g_x + sb * 64 + lane * 2);
                acc.x += wa * ha.x + wb * hb.x;
                acc.y += wa * ha.y + wb * hb.y;
            }
            if (e < s1) {
                int   sa = __ldg(g_csr_src + e);
                float wa = __ldg(g_csr_w + e);
                float2 ha = *reinterpret_cast<const float2*>(g_x + sa * 64 + lane * 2);
                acc.x += wa * ha.x;
                acc.y += wa * ha.y;
            }
        }
        *reinterpret_cast<float2*>(Xs + nl * 64 + lane * 2) = acc;
    }
    __syncthreads();

    // GEMM phase
    int c0 = (tid & 15) * 4, n0 = (tid >> 4) * 8;
    float4 acc[8];
#pragma unroll
    for (int i = 0; i < 8; i++) acc[i] = make_float4(0.f, 0.f, 0.f, 0.f);
    mm_accum8(Xs, Ws, n0, c0, acc);

    // Ws is dead now; reuse its storage for block-local BN stats.
    __syncthreads();
    float* s_stats = Ws;
    if (tid < 128) s_stats[tid] = 0.f;
    __syncthreads();

    float4 b4 = *reinterpret_cast<const float4*>(conv_b + c0);
    float4 ssum = make_float4(0.f, 0.f, 0.f, 0.f);
    float4 ssq  = make_float4(0.f, 0.f, 0.f, 0.f);
#pragma unroll
    for (int i = 0; i < 8; i++) {
        int gn = base + n0 + i;
        if (gn < NN) {
            float4 o = make_float4(acc[i].x + b4.x, acc[i].y + b4.y,
                                   acc[i].z + b4.z, acc[i].w + b4.w);
            *reinterpret_cast<float4*>(g_agg + gn * 64 + c0) = o;
            ssum.x += o.x; ssum.y += o.y; ssum.z += o.z; ssum.w += o.w;
            ssq.x += o.x * o.x; ssq.y += o.y * o.y;
            ssq.z += o.z * o.z; ssq.w += o.w * o.w;
        }
    }
    atomicAdd(&s_stats[c0 + 0], ssum.x);
    atomicAdd(&s_stats[c0 + 1], ssum.y);
    atomicAdd(&s_stats[c0 + 2], ssum.z);
    atomicAdd(&s_stats[c0 + 3], ssum.w);
    atomicAdd(&s_stats[64 + c0 + 0], ssq.x);
    atomicAdd(&s_stats[64 + c0 + 1], ssq.y);
    atomicAdd(&s_stats[64 + c0 + 2], ssq.z);
    atomicAdd(&s_stats[64 + c0 + 3], ssq.w);
    __syncthreads();
    if (tid < 128) atomicAdd(&g_stats[layer * 128 + tid], s_stats[tid]);
}

// ---------------- BN finalize + apply + residual relu ----------------
__global__ void k_bn_apply(const float* __restrict__ gamma,
                           const float* __restrict__ beta, int layer) {
    __shared__ float sc[64], sf[64];
    int tid = threadIdx.x;
    if (tid < 64) {
        float mu  = g_stats[layer * 128 + tid] * (1.0f / NN);
        float var = g_stats[layer * 128 + 64 + tid] * (1.0f / NN) - mu * mu;
        float inv = rsqrtf(var + BN_EPS);
        float gm  = gamma[tid];
        sc[tid] = gm * inv;
        sf[tid] = beta[tid] - mu * inv * gm;
    }
    __syncthreads();
    int i = blockIdx.x * blockDim.x + tid;          // float4 index
    if (i < NN * 16) {
        int c0 = (i & 15) * 4;
        float4 v = reinterpret_cast<const float4*>(g_agg)[i];
        float4 x = reinterpret_cast<const float4*>(g_x)[i];
        x.x += fmaxf(v.x * sc[c0 + 0] + sf[c0 + 0], 0.f);
        x.y += fmaxf(v.y * sc[c0 + 1] + sf[c0 + 1], 0.f);
        x.z += fmaxf(v.z * sc[c0 + 2] + sf[c0 + 2], 0.f);
        x.w += fmaxf(v.w * sc[c0 + 3] + sf[c0 + 3], 0.f);
        reinterpret_cast<float4*>(g_x)[i] = x;
    }
}

// ---------------- link decoder ----------------
__global__ void k_decode(const int* __restrict__ pe, float* __restrict__ out) {
    int w = (blockIdx.x * blockDim.x + threadIdx.x) >> 5;
    int lane = threadIdx.x & 31;
    if (w >= EP) return;
    int a = __ldg(pe + 2 * w);
    int b = __ldg(pe + 2 * w + 1);
    float2 za = __ldg(reinterpret_cast<const float2*>(g_x + a * 64) + lane);
    float2 zb = __ldg(reinterpret_cast<const float2*>(g_x + b * 64) + lane);
    float s = za.x * zb.x + za.y * zb.y;
#pragma unroll
    for (int o = 16; o; o >>= 1) s += __shfl_xor_sync(0xffffffffu, s, o);
    if (lane == 0) out[w] = s;
}

// ---------------- launch ----------------
extern "C" void kernel_launch(void* const* d_in, const int* in_sizes, int n_in,
                              void* d_out, int out_size) {
    const int*   edge_index = (const int*)d_in[0];
    const int*   pred_edge  = (const int*)d_in[1];
    const float* id_emb     = (const float*)d_in[2];
    const float* n2v_emb    = (const float*)d_in[3];
    const float* proj_w     = (const float*)d_in[4];
    const float* proj_b     = (const float*)d_in[5];
    const float* conv_w     = (const float*)d_in[6];
    const float* conv_b     = (const float*)d_in[7];
    const float* bn_gamma   = (const float*)d_in[8];
    const float* bn_beta    = (const float*)d_in[9];
    float*       out        = (float*)d_out;

    const int TB = 256;
    const int GBLK = (NN + 127) / 128;

    k_init      <<<(NN + TB - 1) / TB, TB>>>();
    k_deg_count <<<(EE + TB - 1) / TB, TB>>>(edge_index);
    k_scan_part <<<NB_SCAN, TB>>>();
    k_scan_write<<<NB_SCAN, TB>>>();
    k_csr_fill  <<<(EE + TB - 1) / TB, TB>>>(edge_index);

    k_proj<<<GBLK, TB>>>(id_emb, n2v_emb, proj_w, proj_b);

    for (int l = 0; l < LYR; l++) {
        k_agg     <<<GBLK, TB>>>(conv_w + l * HID * HID, conv_b + l * HID, l);
        k_bn_apply<<<(NN * 16 + TB - 1) / TB, TB>>>(bn_gamma + l * HID, bn_beta + l * HID, l);
    }

    k_decode<<<(EP * 32 + TB - 1) / TB, TB>>>(pred_edge, out);
}

// round 7
// speedup vs baseline: 1.1496x; 1.1496x over previous
#include <cuda_runtime.h>
#include <cuda_fp16.h>
#include <math.h>

#define NN   50000
#define HID  64
#define EE   800000
#define EP   100000
#define LYR  2
#define BN_EPS 1e-5f
#define NB_SCAN 196            // 196 * 256 = 50176 >= NN

// ---------------- scratch ----------------
__device__ float g_x[NN * HID];
__device__ __align__(16) __half g_h[NN * HID];   // fp16 conv output (gather source)
__device__ float g_agg[NN * HID];
__device__ float g_dis[NN];
__device__ int   g_deg[NN];
__device__ int   g_cnt[NN];
__device__ int   g_row_start[NN + 1];
__device__ int2  g_csr[EE];                      // {src, float_as_int(w)}
__device__ int   g_part[256];
__device__ float g_stats[LYR * 2 * HID];         // per layer: sum, sumsq

// ---------------- init ----------------
__global__ void k_init() {
    int n = blockIdx.x * blockDim.x + threadIdx.x;
    if (n < NN) { g_deg[n] = 1; g_cnt[n] = 0; }
    if (n < LYR * 2 * HID) g_stats[n] = 0.f;
    if (n == 0) g_row_start[NN] = EE;
}

__global__ void k_deg_count(const int* __restrict__ ei) {
    int e = blockIdx.x * blockDim.x + threadIdx.x;
    if (e < EE) atomicAdd(&g_deg[ei[EE + e]], 1);
}

// block partial sums of (deg-1), fused with dis = rsqrt(deg)
__global__ void k_scan_part() {
    __shared__ int sh[256];
    int t = threadIdx.x;
    int idx = blockIdx.x * 256 + t;
    int d = (idx < NN) ? g_deg[idx] : 1;
    if (idx < NN) g_dis[idx] = rsqrtf((float)d);
    sh[t] = d - 1;
    __syncthreads();
    for (int o = 128; o > 0; o >>= 1) {
        if (t < o) sh[t] += sh[t + o];
        __syncthreads();
    }
    if (t == 0) g_part[blockIdx.x] = sh[0];
}

// row_start: per-block exclusive scan + inline scan of block partials
__global__ void k_scan_write() {
    __shared__ int shp[256];
    __shared__ int sh[256];
    int t = threadIdx.x;
    int pv = (t < NB_SCAN) ? g_part[t] : 0;
    shp[t] = pv;
    __syncthreads();
    for (int o = 1; o < 256; o <<= 1) {
        int s = (t >= o) ? shp[t - o] : 0;
        __syncthreads();
        shp[t] += s;
        __syncthreads();
    }
    int boff = shp[blockIdx.x] - g_part[blockIdx.x];

    int idx = blockIdx.x * 256 + t;
    int v = (idx < NN) ? g_deg[idx] - 1 : 0;
    sh[t] = v;
    __syncthreads();
    for (int o = 1; o < 256; o <<= 1) {
        int s = (t >= o) ? sh[t - o] : 0;
        __syncthreads();
        sh[t] += s;
        __syncthreads();
    }
    if (idx < NN) g_row_start[idx] = boff + sh[t] - v;
}

__global__ void k_csr_fill(const int* __restrict__ ei) {
    int e = blockIdx.x * blockDim.x + threadIdx.x;
    if (e >= EE) return;
    int r = __ldg(ei + e);
    int c = __ldg(ei + EE + e);
    int pos = g_row_start[c] + atomicAdd(&g_cnt[c], 1);
    float w = __ldg(g_dis + r) * __ldg(g_dis + c);
    g_csr[pos] = make_int2(r, __float_as_int(w));
}

// ============ GEMM helpers: 128x64 block tile, 8x4 thread tile ============
__device__ __forceinline__ void mm_accum8(const float* Xs, const float* Ws,
                                          int n0, int c0, float4 acc[8]) {
#pragma unroll
    for (int k = 0; k < 64; k += 4) {
        float4 wv0 = *reinterpret_cast<const float4*>(Ws + (k + 0) * 64 + c0);
        float4 wv1 = *reinterpret_cast<const float4*>(Ws + (k + 1) * 64 + c0);
        float4 wv2 = *reinterpret_cast<const float4*>(Ws + (k + 2) * 64 + c0);
        float4 wv3 = *reinterpret_cast<const float4*>(Ws + (k + 3) * 64 + c0);
#pragma unroll
        for (int i = 0; i < 8; i++) {
            float4 xv = *reinterpret_cast<const float4*>(Xs + (n0 + i) * 64 + k);
            acc[i].x += xv.x * wv0.x + xv.y * wv1.x + xv.z * wv2.x + xv.w * wv3.x;
            acc[i].y += xv.x * wv0.y + xv.y * wv1.y + xv.z * wv2.y + xv.w * wv3.y;
            acc[i].z += xv.x * wv0.z + xv.y * wv1.z + xv.z * wv2.z + xv.w * wv3.z;
            acc[i].w += xv.x * wv0.w + xv.y * wv1.w + xv.z * wv2.w + xv.w * wv3.w;
        }
    }
}

// ---------------- input projection: x = [id|n2v] @ W + b ----------------
__global__ __launch_bounds__(256) void k_proj(const float* __restrict__ id_emb,
                                              const float* __restrict__ n2v_emb,
                                              const float* __restrict__ W,
                                              const float* __restrict__ b) {
    __shared__ float Xs[128 * 64];
    __shared__ float Ws[64 * 64];
    int tid = threadIdx.x;
    int base = blockIdx.x * 128;
    int c0 = (tid & 15) * 4, n0 = (tid >> 4) * 8;

    float4 acc[8];
#pragma unroll
    for (int i = 0; i < 8; i++) acc[i] = make_float4(0.f, 0.f, 0.f, 0.f);

#pragma unroll
    for (int chunk = 0; chunk < 2; chunk++) {
        const float* src = chunk ? n2v_emb : id_emb;
        for (int j = tid; j < 128 * 16; j += 256) {
            int gn = base + (j >> 4);
            float4 v = make_float4(0.f, 0.f, 0.f, 0.f);
            if (gn < NN) v = *reinterpret_cast<const float4*>(src + gn * 64 + (j & 15) * 4);
            *reinterpret_cast<float4*>(Xs + j * 4) = v;
        }
        const float* Wsrc = W + chunk * 64 * 64;
        for (int j = tid; j < 1024; j += 256)
            *reinterpret_cast<float4*>(Ws + j * 4) =
                *reinterpret_cast<const float4*>(Wsrc + j * 4);
        __syncthreads();
        mm_accum8(Xs, Ws, n0, c0, acc);
        __syncthreads();
    }

    float4 b4 = *reinterpret_cast<const float4*>(b + c0);
#pragma unroll
    for (int i = 0; i < 8; i++) {
        int gn = base + n0 + i;
        if (gn < NN) {
            float4 o = make_float4(acc[i].x + b4.x, acc[i].y + b4.y,
                                   acc[i].z + b4.z, acc[i].w + b4.w);
            *reinterpret_cast<float4*>(g_x + gn * 64 + c0) = o;
        }
    }
}

// ---------------- conv GEMM: h = x @ W, written fp16 ----------------
__global__ __launch_bounds__(256) void k_conv(const float* __restrict__ W) {
    __shared__ float Xs[128 * 64];
    __shared__ float Ws[64 * 64];
    int tid = threadIdx.x;
    int base = blockIdx.x * 128;
    int c0 = (tid & 15) * 4, n0 = (tid >> 4) * 8;

    for (int j = tid; j < 128 * 16; j += 256) {
        int gn = base + (j >> 4);
        float4 v = make_float4(0.f, 0.f, 0.f, 0.f);
        if (gn < NN) v = *reinterpret_cast<const float4*>(g_x + gn * 64 + (j & 15) * 4);
        *reinterpret_cast<float4*>(Xs + j * 4) = v;
    }
    for (int j = tid; j < 1024; j += 256)
        *reinterpret_cast<float4*>(Ws + j * 4) =
            *reinterpret_cast<const float4*>(W + j * 4);
    __syncthreads();

    float4 acc[8];
#pragma unroll
    for (int i = 0; i < 8; i++) acc[i] = make_float4(0.f, 0.f, 0.f, 0.f);
    mm_accum8(Xs, Ws, n0, c0, acc);

#pragma unroll
    for (int i = 0; i < 8; i++) {
        int gn = base + n0 + i;
        if (gn < NN) {
            __half2 h01 = __floats2half2_rn(acc[i].x, acc[i].y);
            __half2 h23 = __floats2half2_rn(acc[i].z, acc[i].w);
            __half2* dst = reinterpret_cast<__half2*>(g_h + gn * 64 + c0);
            dst[0] = h01;
            dst[1] = h23;
        }
    }
}

// ---------------- CSR gather (fp16 source): warp per node + fused BN stats ------
__global__ __launch_bounds__(256) void k_gather(const float* __restrict__ conv_b,
                                                int layer) {
    __shared__ float s_stats[128];
    int tid = threadIdx.x;
    if (tid < 128) s_stats[tid] = 0.f;
    __syncthreads();

    int warp = (blockIdx.x * blockDim.x + tid) >> 5;
    int lane = tid & 31;
    float2 acc = make_float2(0.f, 0.f);

    if (warp < NN) {
        int n = warp;
        int s0 = __ldg(g_row_start + n);
        int s1 = __ldg(g_row_start + n + 1);
        float d = __ldg(g_dis + n);
        float sl = d * d;
        float2 h2 = __half22float2(
            __ldg(reinterpret_cast<const __half2*>(g_h + n * 64) + lane));
        float2 b2 = *reinterpret_cast<const float2*>(conv_b + lane * 2);
        acc.x = b2.x + h2.x * sl;
        acc.y = b2.y + h2.y * sl;

        int e = s0;
        for (; e + 1 < s1; e += 2) {
            int2 ma = __ldg(g_csr + e);
            int2 mb = __ldg(g_csr + e + 1);
            float wa = __int_as_float(ma.y);
            float wb = __int_as_float(mb.y);
            float2 ha = __half22float2(
                __ldg(reinterpret_cast<const __half2*>(g_h + ma.x * 64) + lane));
            float2 hb = __half22float2(
                __ldg(reinterpret_cast<const __half2*>(g_h + mb.x * 64) + lane));
            acc.x += wa * ha.x + wb * hb.x;
            acc.y += wa * ha.y + wb * hb.y;
        }
        if (e < s1) {
            int2 ma = __ldg(g_csr + e);
            float wa = __int_as_float(ma.y);
            float2 ha = __half22float2(
                __ldg(reinterpret_cast<const __half2*>(g_h + ma.x * 64) + lane));
            acc.x += wa * ha.x;
            acc.y += wa * ha.y;
        }
        *reinterpret_cast<float2*>(g_agg + n * 64 + lane * 2) = acc;
    }

    atomicAdd(&s_stats[2 * lane],          acc.x);
    atomicAdd(&s_stats[2 * lane + 1],      acc.y);
    atomicAdd(&s_stats[64 + 2 * lane],     acc.x * acc.x);
    atomicAdd(&s_stats[64 + 2 * lane + 1], acc.y * acc.y);
    __syncthreads();
    if (tid < 128) atomicAdd(&g_stats[layer * 128 + tid], s_stats[tid]);
}

// ---------------- BN finalize + apply + residual relu ----------------
__global__ void k_bn_apply(const float* __restrict__ gamma,
                           const float* __restrict__ beta, int layer) {
    __shared__ float sc[64], sf[64];
    int tid = threadIdx.x;
    if (tid < 64) {
        float mu  = g_stats[layer * 128 + tid] * (1.0f / NN);
        float var = g_stats[layer * 128 + 64 + tid] * (1.0f / NN) - mu * mu;
        float inv = rsqrtf(var + BN_EPS);
        float gm  = gamma[tid];
        sc[tid] = gm * inv;
        sf[tid] = beta[tid] - mu * inv * gm;
    }
    __syncthreads();
    int i = blockIdx.x * blockDim.x + tid;
    if (i < NN * 16) {
        int c0 = (i & 15) * 4;
        float4 v = reinterpret_cast<const float4*>(g_agg)[i];
        float4 x = reinterpret_cast<const float4*>(g_x)[i];
        x.x += fmaxf(v.x * sc[c0 + 0] + sf[c0 + 0], 0.f);
        x.y += fmaxf(v.y * sc[c0 + 1] + sf[c0 + 1], 0.f);
        x.z += fmaxf(v.z * sc[c0 + 2] + sf[c0 + 2], 0.f);
        x.w += fmaxf(v.w * sc[c0 + 3] + sf[c0 + 3], 0.f);
        reinterpret_cast<float4*>(g_x)[i] = x;
    }
}

// ---------------- link decoder ----------------
__global__ void k_decode(const int* __restrict__ pe, float* __restrict__ out) {
    int w = (blockIdx.x * blockDim.x + threadIdx.x) >> 5;
    int lane = threadIdx.x & 31;
    if (w >= EP) return;
    int a = __ldg(pe + 2 * w);
    int b = __ldg(pe + 2 * w + 1);
    float2 za = __ldg(reinterpret_cast<const float2*>(g_x + a * 64) + lane);
    float2 zb = __ldg(reinterpret_cast<const float2*>(g_x + b * 64) + lane);
    float s = za.x * zb.x + za.y * zb.y;
#pragma unroll
    for (int o = 16; o; o >>= 1) s += __shfl_xor_sync(0xffffffffu, s, o);
    if (lane == 0) out[w] = s;
}

// ---------------- launch ----------------
extern "C" void kernel_launch(void* const* d_in, const int* in_sizes, int n_in,
                              void* d_out, int out_size) {
    const int*   edge_index = (const int*)d_in[0];
    const int*   pred_edge  = (const int*)d_in[1];
    const float* id_emb     = (const float*)d_in[2];
    const float* n2v_emb    = (const float*)d_in[3];
    const float* proj_w     = (const float*)d_in[4];
    const float* proj_b     = (const float*)d_in[5];
    const float* conv_w     = (const float*)d_in[6];
    const float* conv_b     = (const float*)d_in[7];
    const float* bn_gamma   = (const float*)d_in[8];
    const float* bn_beta    = (const float*)d_in[9];
    float*       out        = (float*)d_out;

    const int TB = 256;
    const int GBLK = (NN + 127) / 128;

    k_init      <<<(NN + TB - 1) / TB, TB>>>();
    k_deg_count <<<(EE + TB - 1) / TB, TB>>>(edge_index);
    k_scan_part <<<NB_SCAN, TB>>>();
    k_scan_write<<<NB_SCAN, TB>>>();
    k_csr_fill  <<<(EE + TB - 1) / TB, TB>>>(edge_index);

    k_proj<<<GBLK, TB>>>(id_emb, n2v_emb, proj_w, proj_b);

    for (int l = 0; l < LYR; l++) {
        k_conv    <<<GBLK, TB>>>(conv_w + l * HID * HID);
        k_gather  <<<(NN * 32 + TB - 1) / TB, TB>>>(conv_b + l * HID, l);
        k_bn_apply<<<(NN * 16 + TB - 1) / TB, TB>>>(bn_gamma + l * HID, bn_beta + l * HID, l);
    }

    k_decode<<<(EP * 32 + TB - 1) / TB, TB>>>(pred_edge, out);
}